// round 7
// baseline (speedup 1.0000x reference)
#include <cuda_runtime.h>
#include <math.h>
#include <stdint.h>

#define NTOK 64
#define CDIM 256
#define NHEADS 8
#define HD   32
#define QS   260          // row stride (floats) for q/k/v smem buffers
#define NWIN 64
#define NBATCH 2048
#define THREADS 512

#define SMEM_FLOATS (3 * NTOK * QS)
#define SMEM_BYTES  (SMEM_FLOATS * 4)     // 199680 B

__device__ float d_tbl2[225 * NHEADS];
__device__ float d_Tcomb[NWIN * NHEADS * NTOK * NTOK];   // 16*sigmoid(bias)+mask, 8MB
__device__ uint32_t d_wtf[4 * 32768];                    // q,k,v,p weights as tf32 bits

// ---------------- prologue 0: weights -> tf32 bits ----------------
__device__ __forceinline__ uint32_t f2tf(float f) {
    uint32_t u; asm("cvt.rna.tf32.f32 %0, %1;" : "=r"(u) : "f"(f)); return u;
}

__global__ void wconv_kernel(const float* __restrict__ qw, const float* __restrict__ kw,
                             const float* __restrict__ vw, const float* __restrict__ pw) {
    int idx = blockIdx.x * blockDim.x + threadIdx.x;
    if (idx >= 4 * 32768) return;
    int sel = idx >> 15, off = idx & 32767;
    float v = (sel == 0) ? qw[off] : (sel == 1) ? kw[off] : (sel == 2) ? vw[off] : pw[off];
    d_wtf[idx] = f2tf(v);
}

// ---------------- prologue 1: rpb_table -> MLP -> (225, 8) ----------------
__global__ void cpb_mlp_kernel(const float* __restrict__ rpb,
                               const float* __restrict__ w1,
                               const float* __restrict__ b1,
                               const float* __restrict__ w2) {
    __shared__ float acc[NHEADS];
    int p = blockIdx.x;          // 0..224
    int j = threadIdx.x;         // 0..127
    if (j < NHEADS) acc[j] = 0.f;
    __syncthreads();
    float t0 = rpb[p * 2 + 0];
    float t1 = rpb[p * 2 + 1];
    float hid = fmaxf(t0 * w1[j] + t1 * w1[128 + j] + b1[j], 0.f);
#pragma unroll
    for (int h = 0; h < NHEADS; ++h) {
        float pv = hid * w2[j * 8 + h];
#pragma unroll
        for (int o = 16; o; o >>= 1) pv += __shfl_xor_sync(0xffffffffu, pv, o);
        if ((j & 31) == 0) atomicAdd(&acc[h], pv);
    }
    __syncthreads();
    if (j < NHEADS) d_tbl2[p * 8 + j] = acc[j];
}

// ---------------- prologue 2: combined bias+mask table ----------------
__global__ void bias_combine_kernel(const int* __restrict__ rpi,
                                    const float* __restrict__ mask) {
    int idx = blockIdx.x * blockDim.x + threadIdx.x;
    if (idx >= NWIN * NHEADS * NTOK * NTOK) return;
    int ij = idx & 4095;
    int h  = (idx >> 12) & 7;
    int w  = idx >> 15;
    float bv = d_tbl2[rpi[ij] * 8 + h];
    d_Tcomb[idx] = 16.f / (1.f + expf(-bv)) + mask[w * 4096 + ij];
}

// ---------------- mma helper ----------------
__device__ __forceinline__ void mma_tf32(float& d0, float& d1, float& d2, float& d3,
                                         uint32_t a0, uint32_t a1, uint32_t a2, uint32_t a3,
                                         uint32_t b0, uint32_t b1) {
    asm volatile(
        "mma.sync.aligned.m16n8k8.row.col.f32.tf32.tf32.f32 "
        "{%0,%1,%2,%3},{%4,%5,%6,%7},{%8,%9},{%0,%1,%2,%3};"
        : "+f"(d0), "+f"(d1), "+f"(d2), "+f"(d3)
        : "r"(a0), "r"(a1), "r"(a2), "r"(a3), "r"(b0), "r"(b1));
}

// weight source in d_wtf: w 0..3 = q,k,v,p
#define WSRC(w, s, hf) (d_wtf + (w) * 32768 + (s) * 16384 + (hf) * 8192)

// stage buffer for stage index T (compile-time literal after unrolling):
// even -> vsm strip, odd -> kss strip; col region 128 for stages 6..11
#define BUF_PTR(T) ((const uint32_t*)((((T) & 1) ? (void*)kss : (void*)vsm)) + \
                    ((((T) >= 6) && ((T) < 12)) ? 128 : 0))
#define BUF_ADR(T) (((((T) & 1) ? kss_u : vsm_u)) + ((((T) >= 6) && ((T) < 12)) ? 512u : 0u))

// issue the 4 cp.async for one [64][128] weight stage + commit (512 threads)
#define ISSUE(SRC, DSTU) do {                                                \
    const uint32_t* _s0 = (SRC) + ldrow * 128 + ldcol;                       \
    uint32_t _d0 = (DSTU) + (uint32_t)((ldrow * QS + ldcol) * 4);            \
    _Pragma("unroll")                                                        \
    for (int k_ = 0; k_ < 4; ++k_)                                           \
        asm volatile("cp.async.cg.shared.global [%0], [%1], 16;\n"           \
            :: "r"(_d0 + (uint32_t)(k_ * 16 * QS * 4)),                      \
               "l"(_s0 + k_ * 16 * 128) : "memory");                         \
    asm volatile("cp.async.commit_group;\n" ::: "memory");                   \
} while (0)

// 16x32 warp-tile mma over one staged [64 K][128 N] weight tile
#define MMA_LOOP16(BUFP, ACC) do {                                           \
    const uint32_t* _bu = (BUFP);                                            \
    _Pragma("unroll")                                                        \
    for (int kt = 0; kt < 8; ++kt) {                                         \
        const uint32_t* bp = _bu + (kt * 8 + ql) * QS + n0 + qr;             \
        _Pragma("unroll")                                                    \
        for (int nt = 0; nt < 4; ++nt) {                                     \
            mma_tf32(ACC[nt][0], ACC[nt][1], ACC[nt][2], ACC[nt][3],         \
                     af[kt][0], af[kt][1], af[kt][2], af[kt][3],             \
                     bp[nt * 8], bp[4 * QS + nt * 8]);                       \
        }                                                                    \
    }                                                                        \
} while (0)

// pipelined stage: wait prefetched group, sync, prefetch next, mma current
#define STAGE(NEXTSRC, NEXTDSTU, CURBUF, ACC) do {                           \
    asm volatile("cp.async.wait_group 0;\n" ::: "memory");                   \
    __syncthreads();                                                         \
    { const uint32_t* _ns = (NEXTSRC); if (_ns) ISSUE(_ns, NEXTDSTU); }      \
    MMA_LOOP16(CURBUF, ACC);                                                 \
} while (0)

#define LOAD_AF_F32(CB) do {                                                 \
    _Pragma("unroll")                                                        \
    for (int kt = 0; kt < 8; ++kt) {                                         \
        const float* ap = qs + (r0 + qr) * QS + (CB) + kt * 8 + ql;          \
        af[kt][0] = f2tf(ap[0]);                                             \
        af[kt][1] = f2tf(ap[8 * QS]);                                        \
        af[kt][2] = f2tf(ap[4]);                                             \
        af[kt][3] = f2tf(ap[8 * QS + 4]);                                    \
    }                                                                        \
} while (0)

#define LOAD_AF_BITS(CB) do {                                                \
    _Pragma("unroll")                                                        \
    for (int kt = 0; kt < 8; ++kt) {                                         \
        const uint32_t* ap = qsu + (r0 + qr) * QS + (CB) + kt * 8 + ql;      \
        af[kt][0] = ap[0];                                                   \
        af[kt][1] = ap[8 * QS];                                              \
        af[kt][2] = ap[4];                                                   \
        af[kt][3] = ap[8 * QS + 4];                                          \
    }                                                                        \
} while (0)

// ---------------- main fused kernel: one CTA per window, 512 threads ----------------
__global__ void __launch_bounds__(THREADS, 1)
swin_block_kernel(const float* __restrict__ x,
                  const float* __restrict__ qb, const float* __restrict__ kb,
                  const float* __restrict__ vb, const float* __restrict__ pb,
                  const float* __restrict__ ls, float* __restrict__ out)
{
    extern __shared__ float sm[];
    float* qs  = sm;
    float* kss = sm + NTOK * QS;
    float* vsm = sm + 2 * NTOK * QS;
    const uint32_t* qsu = (const uint32_t*)qs;
    uint32_t* qsw = (uint32_t*)qs;
    uint32_t* ksw = (uint32_t*)kss;
    uint32_t* vsw = (uint32_t*)vsm;

    const int b    = blockIdx.x;
    const int tid  = threadIdx.x;
    const int warp = tid >> 5;
    const int lane = tid & 31;
    const int r0   = (warp & 3) * 16;       // GEMM warp row tile (4 tiles)
    const int n0   = (warp >> 2) * 32;      // GEMM warp col tile (4 tiles)
    const int qr   = lane >> 2;             // quad row 0..7
    const int ql   = lane & 3;              // quad col 0..3
    const int ldrow = tid >> 5;             // staging row base 0..15
    const int ldcol = (tid & 31) * 4;       // staging col 0..124

    const uint32_t vsm_u = (uint32_t)__cvta_generic_to_shared(vsm);
    const uint32_t kss_u = (uint32_t)__cvta_generic_to_shared(kss);

    uint32_t af[8][4];

    // prefetch stage 0 (qw s0 hf0) into vsm strip
    ISSUE(WSRC(0, 0, 0), BUF_ADR(0));

    // load x [64][256] into qs (fp32, stride QS)
    const float* xg = x + (size_t)b * (NTOK * CDIM);
    for (int t = tid; t < 64 * 64; t += THREADS) {
        int i = t >> 6, c4 = t & 63;
        *(float4*)&qs[i * QS + c4 * 4] = ((const float4*)xg)[i * 64 + c4];
    }
    __syncthreads();   // x visible to ALL warps before any A-fragment load

    // =========== Phase 1: QKV dual-branch residual linears ===========
#pragma unroll
    for (int s = 0; s < 2; ++s) {
        float accQ[4][4], accK[4][4], accV[4][4];
#pragma unroll
        for (int nt = 0; nt < 4; ++nt)
#pragma unroll
            for (int e = 0; e < 4; ++e) {
                accQ[nt][e] = 0.f; accK[nt][e] = 0.f; accV[nt][e] = 0.f;
            }

#pragma unroll
        for (int hf = 0; hf < 2; ++hf) {
            LOAD_AF_F32(s * 128 + hf * 64);
            const int t0 = (s * 2 + hf) * 3;
            STAGE(WSRC(1, s, hf), BUF_ADR(t0 + 1), BUF_PTR(t0 + 0), accQ);
            STAGE(WSRC(2, s, hf), BUF_ADR(t0 + 2), BUF_PTR(t0 + 1), accK);
            const uint32_t* nxt = (hf == 0) ? WSRC(0, s, 1)
                                : (s == 0)  ? WSRC(0, 1, 0) : (const uint32_t*)0;
            STAGE(nxt, BUF_ADR(t0 + 3 < 12 ? t0 + 3 : 0), BUF_PTR(t0 + 2), accV);
        }
        __syncthreads();   // all mma reads of staged weights done before epilogue writes

        // epilogue: residual + bias; k,q fp32 (normalized later), v as tf32 bits
        {
            const int rr = r0 + qr;
            const float* x0p = qs + rr * QS + s * 128;
            const float* x1p = x0p + 8 * QS;
#pragma unroll
            for (int nt = 0; nt < 4; ++nt) {
                const int c = n0 + nt * 8 + 2 * ql;
                float2 x0 = *(const float2*)&x0p[c];
                float2 x1 = *(const float2*)&x1p[c];
                float2 kb2 = *(const float2*)&kb[s * 128 + c];
                float2 vb2 = *(const float2*)&vb[s * 128 + c];
                float2 qb2 = *(const float2*)&qb[s * 128 + c];
                *(float2*)&kss[rr * QS + s * 128 + c] =
                    make_float2(x0.x + accK[nt][0] + kb2.x, x0.y + accK[nt][1] + kb2.y);
                *(float2*)&kss[(rr + 8) * QS + s * 128 + c] =
                    make_float2(x1.x + accK[nt][2] + kb2.x, x1.y + accK[nt][3] + kb2.y);
                *(uint2*)&vsw[rr * QS + s * 128 + c] =
                    make_uint2(f2tf(x0.x + accV[nt][0] + vb2.x), f2tf(x0.y + accV[nt][1] + vb2.y));
                *(uint2*)&vsw[(rr + 8) * QS + s * 128 + c] =
                    make_uint2(f2tf(x1.x + accV[nt][2] + vb2.x), f2tf(x1.y + accV[nt][3] + vb2.y));
                *(float2*)&qs[rr * QS + s * 128 + c] =
                    make_float2(x0.x + accQ[nt][0] + qb2.x, x0.y + accQ[nt][1] + qb2.y);
                *(float2*)&qs[(rr + 8) * QS + s * 128 + c] =
                    make_float2(x1.x + accQ[nt][2] + qb2.x, x1.y + accQ[nt][3] + qb2.y);
            }
        }
        __syncthreads();
    }

    // =========== Phase 2: l2-normalize q,k; fold logit scale; store tf32 bits ===========
#pragma unroll
    for (int t4 = 0; t4 < 2; ++t4) {
        int t = tid + t4 * THREADS;      // 1024 tasks
        int bufsel = t >> 9;
        int h = (t >> 6) & 7;
        int i = t & 63;
        float* base = (bufsel ? kss : qs) + i * QS + h * HD;
        uint32_t* baseu = (uint32_t*)base;
        float4 vv[8];
        float ssq = 0.f;
#pragma unroll
        for (int u = 0; u < 8; ++u) {
            vv[u] = ((float4*)base)[u];
            ssq = fmaf(vv[u].x, vv[u].x, ssq);
            ssq = fmaf(vv[u].y, vv[u].y, ssq);
            ssq = fmaf(vv[u].z, vv[u].z, ssq);
            ssq = fmaf(vv[u].w, vv[u].w, ssq);
        }
        float inv = 1.f / fmaxf(sqrtf(ssq), 1e-12f);
        if (bufsel == 0) inv *= fminf(expf(ls[h]), 100.f);
#pragma unroll
        for (int u = 0; u < 8; ++u) {
            uint4 st;
            st.x = f2tf(vv[u].x * inv); st.y = f2tf(vv[u].y * inv);
            st.z = f2tf(vv[u].z * inv); st.w = f2tf(vv[u].w * inv);
            ((uint4*)baseu)[u] = st;
        }
    }
    __syncthreads();

    // =========== Phase 3: attention via tf32 mma, two warps per head ===========
    {
        const int h = warp >> 1;                 // head
        const int mtb = (warp & 1) * 2;          // this warp's 2 row tiles
        const float* Tw = d_Tcomb + (size_t)(((b & (NWIN - 1)) * NHEADS + h) << 12);
        const int s0l = (lane & ~3) | (ql >> 1);
        const bool odd = ql & 1;

#pragma unroll 1
        for (int mm = 0; mm < 2; ++mm) {
            const int i0r = (mtb + mm) * 16 + qr;

            uint32_t qa[4][4];
#pragma unroll
            for (int kt = 0; kt < 4; ++kt) {
                const uint32_t* ap = qsu + i0r * QS + h * HD + kt * 8 + ql;
                qa[kt][0] = ap[0];
                qa[kt][1] = ap[8 * QS];
                qa[kt][2] = ap[4];
                qa[kt][3] = ap[8 * QS + 4];
            }

            float S[8][4];
#pragma unroll
            for (int nt = 0; nt < 8; ++nt) { S[nt][0] = S[nt][1] = S[nt][2] = S[nt][3] = 0.f; }
#pragma unroll
            for (int kt = 0; kt < 4; ++kt) {
#pragma unroll
                for (int nt = 0; nt < 8; ++nt) {
                    const uint32_t* kp = (const uint32_t*)kss + (nt * 8 + qr) * QS + h * HD + kt * 8 + ql;
                    mma_tf32(S[nt][0], S[nt][1], S[nt][2], S[nt][3],
                             qa[kt][0], qa[kt][1], qa[kt][2], qa[kt][3], kp[0], kp[4]);
                }
            }

            float rmax0 = -1e30f, rmax1 = -1e30f;
#pragma unroll
            for (int nt = 0; nt < 8; ++nt) {
                float2 t0 = *(const float2*)&Tw[i0r * 64 + nt * 8 + 2 * ql];
                float2 t1 = *(const float2*)&Tw[(i0r + 8) * 64 + nt * 8 + 2 * ql];
                S[nt][0] += t0.x; S[nt][1] += t0.y;
                S[nt][2] += t1.x; S[nt][3] += t1.y;
                rmax0 = fmaxf(rmax0, fmaxf(S[nt][0], S[nt][1]));
                rmax1 = fmaxf(rmax1, fmaxf(S[nt][2], S[nt][3]));
            }
            rmax0 = fmaxf(rmax0, __shfl_xor_sync(0xffffffffu, rmax0, 1));
            rmax0 = fmaxf(rmax0, __shfl_xor_sync(0xffffffffu, rmax0, 2));
            rmax1 = fmaxf(rmax1, __shfl_xor_sync(0xffffffffu, rmax1, 1));
            rmax1 = fmaxf(rmax1, __shfl_xor_sync(0xffffffffu, rmax1, 2));

            float sum0 = 0.f, sum1 = 0.f;
#pragma unroll
            for (int nt = 0; nt < 8; ++nt) {
                S[nt][0] = __expf(S[nt][0] - rmax0); sum0 += S[nt][0];
                S[nt][1] = __expf(S[nt][1] - rmax0); sum0 += S[nt][1];
                S[nt][2] = __expf(S[nt][2] - rmax1); sum1 += S[nt][2];
                S[nt][3] = __expf(S[nt][3] - rmax1); sum1 += S[nt][3];
            }
            sum0 += __shfl_xor_sync(0xffffffffu, sum0, 1);
            sum0 += __shfl_xor_sync(0xffffffffu, sum0, 2);
            sum1 += __shfl_xor_sync(0xffffffffu, sum1, 1);
            sum1 += __shfl_xor_sync(0xffffffffu, sum1, 2);
            float inv0 = 1.f / sum0, inv1 = 1.f / sum1;

            uint32_t pa[8][4];
#pragma unroll
            for (int nt = 0; nt < 8; ++nt) {
                uint32_t u0 = f2tf(S[nt][0]), u1 = f2tf(S[nt][1]);
                uint32_t u2 = f2tf(S[nt][2]), u3 = f2tf(S[nt][3]);
                uint32_t v0 = __shfl_sync(0xffffffffu, u0, s0l);
                uint32_t v1 = __shfl_sync(0xffffffffu, u1, s0l);
                pa[nt][0] = odd ? v1 : v0;
                uint32_t v2 = __shfl_sync(0xffffffffu, u2, s0l);
                uint32_t v3 = __shfl_sync(0xffffffffu, u3, s0l);
                pa[nt][1] = odd ? v3 : v2;
                v0 = __shfl_sync(0xffffffffu, u0, s0l + 2);
                v1 = __shfl_sync(0xffffffffu, u1, s0l + 2);
                pa[nt][2] = odd ? v1 : v0;
                v2 = __shfl_sync(0xffffffffu, u2, s0l + 2);
                v3 = __shfl_sync(0xffffffffu, u3, s0l + 2);
                pa[nt][3] = odd ? v3 : v2;
            }

            float O[4][4];
#pragma unroll
            for (int nd = 0; nd < 4; ++nd) { O[nd][0] = O[nd][1] = O[nd][2] = O[nd][3] = 0.f; }
#pragma unroll
            for (int kt = 0; kt < 8; ++kt) {
#pragma unroll
                for (int nd = 0; nd < 4; ++nd) {
                    const uint32_t* vp = (const uint32_t*)vsm + (kt * 8 + ql) * QS + h * HD + nd * 8 + qr;
                    mma_tf32(O[nd][0], O[nd][1], O[nd][2], O[nd][3],
                             pa[kt][0], pa[kt][1], pa[kt][2], pa[kt][3], vp[0], vp[4 * QS]);
                }
            }

#pragma unroll
            for (int nd = 0; nd < 4; ++nd) {
                uint2 st0, st1;
                st0.x = f2tf(O[nd][0] * inv0); st0.y = f2tf(O[nd][1] * inv0);
                st1.x = f2tf(O[nd][2] * inv1); st1.y = f2tf(O[nd][3] * inv1);
                *(uint2*)&qsw[i0r * QS + h * HD + nd * 8 + 2 * ql] = st0;
                *(uint2*)&qsw[(i0r + 8) * QS + h * HD + nd * 8 + 2 * ql] = st1;
            }
        }
    }
    __syncthreads();   // all O (tf32 bits) written; vsm/kss now dead

    // =========== Phase 4: output projection, store to gmem ===========
    float* og = out + (size_t)b * (NTOK * CDIM);
    ISSUE(WSRC(3, 0, 0), BUF_ADR(12));     // prefetch first proj stage
#pragma unroll
    for (int s = 0; s < 2; ++s) {
        float accP[4][4];
#pragma unroll
        for (int nt = 0; nt < 4; ++nt)
#pragma unroll
            for (int e = 0; e < 4; ++e) accP[nt][e] = 0.f;

#pragma unroll
        for (int hf = 0; hf < 2; ++hf) {
            LOAD_AF_BITS(s * 128 + hf * 64);
            const int t = 12 + s * 2 + hf;
            const uint32_t* nxt = (t < 15) ? WSRC(3, (t - 11) >> 1, (t - 11) & 1)
                                           : (const uint32_t*)0;
            STAGE(nxt, BUF_ADR((t + 1) & 15), BUF_PTR(t), accP);
        }
        {
            const int rr = r0 + qr;
#pragma unroll
            for (int nt = 0; nt < 4; ++nt) {
                const int c = n0 + nt * 8 + 2 * ql;
                float2 pb2 = *(const float2*)&pb[s * 128 + c];
                *(float2*)&og[rr * CDIM + s * 128 + c] =
                    make_float2(accP[nt][0] + pb2.x, accP[nt][1] + pb2.y);
                *(float2*)&og[(rr + 8) * CDIM + s * 128 + c] =
                    make_float2(accP[nt][2] + pb2.x, accP[nt][3] + pb2.y);
            }
        }
    }
}

extern "C" void kernel_launch(void* const* d_in, const int* in_sizes, int n_in,
                              void* d_out, int out_size) {
    const float* x    = (const float*)d_in[0];
    const float* mask = (const float*)d_in[1];
    const float* qw   = (const float*)d_in[2];
    const float* qb   = (const float*)d_in[3];
    const float* kw   = (const float*)d_in[4];
    const float* kb   = (const float*)d_in[5];
    const float* vw   = (const float*)d_in[6];
    const float* vb   = (const float*)d_in[7];
    const float* pw   = (const float*)d_in[8];
    const float* pb   = (const float*)d_in[9];
    const float* w1   = (const float*)d_in[10];
    const float* b1   = (const float*)d_in[11];
    const float* w2   = (const float*)d_in[12];
    const float* ls   = (const float*)d_in[13];
    const float* rpb  = (const float*)d_in[14];
    const int*   rpi  = (const int*)d_in[15];
    float* out = (float*)d_out;

    static bool inited = false;
    if (!inited) {
        cudaFuncSetAttribute(swin_block_kernel,
                             cudaFuncAttributeMaxDynamicSharedMemorySize, SMEM_BYTES);
        inited = true;
    }

    wconv_kernel<<<512, 256>>>(qw, kw, vw, pw);
    cpb_mlp_kernel<<<225, 128>>>(rpb, w1, b1, w2);
    bias_combine_kernel<<<(NWIN * NHEADS * NTOK * NTOK + 255) / 256, 256>>>(rpi, mask);
    swin_block_kernel<<<NBATCH, THREADS, SMEM_BYTES>>>(x, qb, kb, vb, pb, ls, out);
}